// round 11
// baseline (speedup 1.0000x reference)
#include <cuda_runtime.h>
#include <cuda_fp16.h>
#include <math.h>
#include <stdint.h>

// ---------------- problem constants ----------------
#define NB 16
#define HW 4096
#define CHW (128*HW)          // 524288
#define AUXC 277
#define AUXK 320

// ---------------- weight pack offsets (halfs) ----------------
#define WO_QKV  0             // [384][128]
#define WO_E1   49152         // [128][320]
#define WO_GB1  90112         // [256][128]
#define WO_B1   122880        // [128][256]
#define WO_E2   155648
#define WO_GB2  196608
#define WO_B2   229376
#define WO_SC   262144        // [128][1152] plane-major
#define WO_BI1  409600
#define WO_BI2  557056
#define W_TOTAL 704512

// ---------------- scratch ----------------
__device__ __align__(256) half  g_wh  [W_TOTAL];
__device__ float g_qkvb[384];
__device__ float g_gbb1[256];
__device__ float g_gbb2[256];
__device__ __align__(256) half  g_auxh[(long)NB*AUXK*HW];
__device__ __align__(256) half  g_xh  [(long)NB*CHW];
__device__ __align__(256) half  g_ah  [(long)NB*CHW];
__device__ __align__(256) half  g_t0h [(long)NB*3*CHW];
__device__ __align__(256) half  g_gamh[(long)NB*CHW];
__device__ __align__(256) half  g_beth[(long)NB*CHW];
__device__ __align__(256) half  g_midh[(long)NB*CHW];
__device__ __align__(256) half  g_oh  [(long)NB*CHW];
__device__ __align__(256) half  g_gfh [(long)NB*CHW];
__device__ __align__(256) half  g_tmph[(long)NB*CHW];
__device__ __align__(256) half  g_qp1 [NB*1024L*256];
__device__ __align__(256) half  g_kp1 [NB*1024L*256];
__device__ __align__(256) half  g_vp1 [NB*1024L*256];
__device__ __align__(256) half  g_qp2 [NB*256L*1024];
__device__ __align__(256) half  g_kp2 [NB*256L*1024];
__device__ __align__(256) half  g_vp2 [NB*256L*1024];
__device__ __align__(256) half  g_s1h [NB*1024L*1024];
__device__ __align__(256) half  g_s2h [NB*256L*256];
__device__ float g_stats[96];
__device__ float g_acc  [96];

// ---------------- epilogue modes ----------------
#define EP_LIN   0
#define EP_GB    1
#define EP_QKV3  2
#define EP_ADN   3
#define EP_SCORE 4
#define EP_PV1   5
#define EP_PV2   6
#define EP_TANH  7
#define EP_GELU  8
#define EP_FINAL 9

// ---------------- smem geometry (halfs), Kt = 64 ----------------
#define A_LDH 72
#define A_ROWB 144
#define BK_LDH 136
#define BK_ROWB 272
#define STAGE_HALFS 18432
#define STAGE_BYTES 36864
#define B_OFF_H 9216
#define GSM_BYTES (2*STAGE_BYTES)

// ---------------- asm helpers ----------------
__device__ __forceinline__ uint32_t smem_u32(const void* p) {
    uint32_t a;
    asm("{ .reg .u64 t; cvta.to.shared.u64 t, %1; cvt.u32.u64 %0, t; }" : "=r"(a) : "l"(p));
    return a;
}
__device__ __forceinline__ void ldsm_x4(uint32_t* r, uint32_t addr) {
    asm volatile("ldmatrix.sync.aligned.m8n8.x4.shared.b16 {%0,%1,%2,%3}, [%4];"
                 : "=r"(r[0]), "=r"(r[1]), "=r"(r[2]), "=r"(r[3]) : "r"(addr));
}
__device__ __forceinline__ void ldsm_x4t(uint32_t* r, uint32_t addr) {
    asm volatile("ldmatrix.sync.aligned.m8n8.x4.trans.shared.b16 {%0,%1,%2,%3}, [%4];"
                 : "=r"(r[0]), "=r"(r[1]), "=r"(r[2]), "=r"(r[3]) : "r"(addr));
}
__device__ __forceinline__ void mma_f16(float* c,
                                        uint32_t a0, uint32_t a1, uint32_t a2, uint32_t a3,
                                        uint32_t b0, uint32_t b1) {
    asm volatile(
        "mma.sync.aligned.m16n8k16.row.col.f32.f16.f16.f32 "
        "{%0,%1,%2,%3}, {%4,%5,%6,%7}, {%8,%9}, {%0,%1,%2,%3};"
        : "+f"(c[0]), "+f"(c[1]), "+f"(c[2]), "+f"(c[3])
        : "r"(a0), "r"(a1), "r"(a2), "r"(a3), "r"(b0), "r"(b1));
}

// ---------------- GEMM params ----------------
struct GP {
    const half* A; int lda; long sA;
    const half* B; int ldb; long sB;
    int N; long sC; int nkt;
    int mode; float scale; int dil; int lng;
    const float* bias;
    const half* t0h; const half* gamh; const half* beth; const float* stats;
    const float* xres; const half* midh; const half* gfh;
    float* of; half* ohh; half* ohh2;
    half* d1q; half* d1k; half* d1v;
    half* d2q; half* d2k; half* d2v;
    float* acc;
};

// ================= fp16 tensor-core GEMM, Kt=64 =================
// TRANSB=0, CONV=0 : C[m,n] = A[m,k] * B[k,n]   (B k-major smem, ldmatrix.trans)
// TRANSB=1         : C[m,n] = A[m,k] * B[n,k]   (B n-major smem, ldmatrix)
// CONV=1           : B gathered vectorized from NCHW-half activations (k-major smem)
template<bool TRANSB, bool CONV>
__global__ void __launch_bounds__(256)
hgemm11(GP g) {
    extern __shared__ __align__(16) half sm[];
    int bb = blockIdx.z;
    int n0 = blockIdx.x * 128;
    int m0 = blockIdx.y * 128;
    const half* Ap = g.A + (long)bb * g.sA;
    const half* Bp = g.B + (long)bb * g.sB;

    int tid  = threadIdx.x;
    int lane = tid & 31;
    int warp = tid >> 5;
    int wm = (warp >> 2) * 64;
    int wn = (warp & 3) * 32;

    int arow  = tid >> 1;
    int akseg = (tid & 1) * 32;
    int bkr = tid >> 2;
    int bns = (tid & 3) * 32;
    // CONV loader: 16 pixels x 2 channels per thread
    int pg   = tid & 7;            // pixel group (16 px)
    int cgi2 = (tid >> 3) * 2;     // channel pair base (0..62)
    int hrow = (n0 + pg * 16) >> 6;
    int w0   = (pg * 16) & 63;

    uint32_t sbase = smem_u32(sm);
    int rowsel = lane & 15;
    int colsel = (lane >> 4) * 16;

    uint4 ra[4], rb[4];
    uint32_t ov[2][8];
    float acc[4][4][4] = {};
    int nkt = g.nkt;

    for (int it = 0; it <= nkt; it++) {
        if (it < nkt) {
            int kt = it * 64;
            const half* ar = Ap + (long)(m0 + arow) * g.lda + kt + akseg;
#pragma unroll
            for (int j = 0; j < 4; j++) ra[j] = *(const uint4*)(ar + j * 8);
            if (CONV) {
                int tap = kt >> 7;
                int cb  = kt & 127;
                int dy  = (tap / 3 - 1) * g.dil;
                int dxc = (tap % 3 - 1) * g.dil;
                int gh  = hrow + dy;
                if ((unsigned)gh < 64u) {
#pragma unroll
                    for (int j = 0; j < 2; j++) {
                        const half* R = Bp + (long)(cb + cgi2 + j) * HW + gh * 64;
                        uint4 C0 = make_uint4(0u,0u,0u,0u), C3 = make_uint4(0u,0u,0u,0u);
                        if (dxc < 0 && w0 > 0)  C0 = *(const uint4*)(R + w0 - 8);
                        uint4 C1 = *(const uint4*)(R + w0);
                        uint4 C2 = *(const uint4*)(R + w0 + 8);
                        if (dxc > 0 && w0 < 48) C3 = *(const uint4*)(R + w0 + 16);
                        uint32_t v[16] = {C0.x,C0.y,C0.z,C0.w, C1.x,C1.y,C1.z,C1.w,
                                          C2.x,C2.y,C2.z,C2.w, C3.x,C3.y,C3.z,C3.w};
                        uint32_t* oj = ov[j];
                        if (dxc == 0) {
#pragma unroll
                            for (int k2 = 0; k2 < 8; k2++) oj[k2] = v[4 + k2];
                        } else if (dxc == -1) {
#pragma unroll
                            for (int k2 = 0; k2 < 8; k2++)
                                oj[k2] = __byte_perm(v[3 + k2], v[4 + k2], 0x5432);
                        } else if (dxc == 1) {
#pragma unroll
                            for (int k2 = 0; k2 < 8; k2++)
                                oj[k2] = __byte_perm(v[4 + k2], v[5 + k2], 0x5432);
                        } else if (dxc == -2) {
#pragma unroll
                            for (int k2 = 0; k2 < 8; k2++) oj[k2] = v[3 + k2];
                        } else {
#pragma unroll
                            for (int k2 = 0; k2 < 8; k2++) oj[k2] = v[5 + k2];
                        }
                    }
                } else {
#pragma unroll
                    for (int j = 0; j < 2; j++)
#pragma unroll
                        for (int k2 = 0; k2 < 8; k2++) ov[j][k2] = 0u;
                }
            } else if (TRANSB) {
                const half* br = Bp + (long)(n0 + arow) * g.ldb + kt + akseg;
#pragma unroll
                for (int j = 0; j < 4; j++) rb[j] = *(const uint4*)(br + j * 8);
            } else {
                const half* br = Bp + (long)(kt + bkr) * g.ldb + n0 + bns;
#pragma unroll
                for (int j = 0; j < 4; j++) rb[j] = *(const uint4*)(br + j * 8);
            }
        }

        if (it > 0) {
            uint32_t stA = sbase + (uint32_t)(((it - 1) & 1) * STAGE_BYTES);
            uint32_t stB = stA + B_OFF_H * 2;
            uint32_t abase = stA + (uint32_t)(wm + rowsel) * A_ROWB + colsel;
#pragma unroll
            for (int ks = 0; ks < 4; ks++) {
                uint32_t af[4][4];
#pragma unroll
                for (int mt = 0; mt < 4; mt++)
                    ldsm_x4(af[mt], abase + mt * 16 * A_ROWB + ks * 32);
                uint32_t bf[2][4];
                if (TRANSB) {
                    uint32_t bbase = stB + (uint32_t)(wn + rowsel) * A_ROWB + colsel;
#pragma unroll
                    for (int ntp = 0; ntp < 2; ntp++)
                        ldsm_x4(bf[ntp], bbase + ntp * 16 * A_ROWB + ks * 32);
                } else {
                    uint32_t bbase = stB + (uint32_t)(ks * 16 + rowsel) * BK_ROWB
                                   + (uint32_t)(wn + (lane >> 4) * 8) * 2;
#pragma unroll
                    for (int ntp = 0; ntp < 2; ntp++)
                        ldsm_x4t(bf[ntp], bbase + ntp * 32);
                }
#pragma unroll
                for (int mt = 0; mt < 4; mt++) {
#pragma unroll
                    for (int nt = 0; nt < 4; nt++) {
                        int ntp = nt >> 1, par = nt & 1;
                        uint32_t b0, b1;
                        if (TRANSB) { b0 = bf[ntp][par];     b1 = bf[ntp][par + 2]; }
                        else        { b0 = bf[ntp][par * 2]; b1 = bf[ntp][par * 2 + 1]; }
                        mma_f16(acc[mt][nt],
                                af[mt][0], af[mt][1], af[mt][2], af[mt][3], b0, b1);
                    }
                }
            }
        }

        if (it < nkt) {
            half* stA = sm + (it & 1) * STAGE_HALFS;
            half* stB = stA + B_OFF_H;
            half* da = stA + arow * A_LDH + akseg;
#pragma unroll
            for (int j = 0; j < 4; j++) *(uint4*)(da + j * 8) = ra[j];
            if (CONV) {
                half* db = stB + cgi2 * BK_LDH + pg * 16;
                *(uint4*)db       = make_uint4(ov[0][0], ov[0][1], ov[0][2], ov[0][3]);
                *(uint4*)(db + 8) = make_uint4(ov[0][4], ov[0][5], ov[0][6], ov[0][7]);
                *(uint4*)(db + BK_LDH)     = make_uint4(ov[1][0], ov[1][1], ov[1][2], ov[1][3]);
                *(uint4*)(db + BK_LDH + 8) = make_uint4(ov[1][4], ov[1][5], ov[1][6], ov[1][7]);
            } else if (TRANSB) {
                half* db = stB + arow * A_LDH + akseg;
#pragma unroll
                for (int j = 0; j < 4; j++) *(uint4*)(db + j * 8) = rb[j];
            } else {
                half* db = stB + bkr * BK_LDH + bns;
#pragma unroll
                for (int j = 0; j < 4; j++) *(uint4*)(db + j * 8) = rb[j];
            }
        }
        __syncthreads();
    }

    // ---- epilogue ----
    int r  = lane >> 2;
    int cg = lane & 3;
    int mode = g.mode;
    int N = g.N;
    long bbC = (long)bb * g.sC;
    float mu = 0.f, rs = 0.f;
    if (mode == EP_QKV3 || mode == EP_ADN) { mu = g.stats[2 * bb]; rs = g.stats[2 * bb + 1]; }
    int b3 = bb / 3, t3 = bb - 3 * (bb / 3);
    float lsum = 0.f, lsq = 0.f;

    auto emit = [&](float v, int m, int n) {
        long li = (long)m * N + n;
        if (mode == EP_LIN) {
            float res = v + g.bias[m];
            if (g.lng) { lsum += res; lsq += res * res; }
            g.ohh[bbC + li] = __float2half_rn(res);
        } else if (mode == EP_GB) {
            float res = v + g.bias[m];
            long o = (long)bb * CHW + (long)(m & 127) * HW + n;
            if (m < 128) g.ohh [o] = __float2half_rn(res);
            else         g.ohh2[o] = __float2half_rn(res);
        } else if (mode == EP_QKV3) {
            long ti = bbC + li;
            long gi = (long)b3 * CHW + li;
            float val = (__half2float(g.t0h[ti]) - mu) * rs * __half2float(g.gamh[gi])
                        + v + __half2float(g.beth[gi]);
            half hv = __float2half_rn(val);
            int h = n >> 6, w = n & 63;
            if (m < 64) {
                int tk = (h >> 1) * 32 + (w >> 1);
                int d  = m * 4 + (h & 1) * 2 + (w & 1);
                half* dst = (t3 == 0) ? g.d1q : (t3 == 1) ? g.d1k : g.d1v;
                dst[(long)b3 * (1024L * 256) + (long)tk * 256 + d] = hv;
            } else {
                int tk = (h >> 2) * 16 + (w >> 2);
                int d  = (m - 64) * 16 + (h & 3) * 4 + (w & 3);
                half* dst = (t3 == 0) ? g.d2q : (t3 == 1) ? g.d2k : g.d2v;
                dst[(long)b3 * (256L * 1024) + (long)tk * 1024 + d] = hv;
            }
        } else if (mode == EP_ADN) {
            long gi = bbC + li;
            float res = (__half2float(g.t0h[gi]) - mu) * rs * __half2float(g.gamh[gi])
                        + v + __half2float(g.beth[gi]);
            g.ohh[gi] = __float2half_rn(res);
        } else if (mode == EP_SCORE) {
            g.ohh[bbC + li] = __float2half_rn(v * g.scale);
        } else if (mode == EP_PV1) {
            int c  = n >> 2;
            int py = (n >> 1) & 1, px = n & 1;
            int h = (m >> 5) * 2 + py, w = (m & 31) * 2 + px;
            long tgt = bbC + (long)c * HW + h * 64 + w;
            float res = g.xres[tgt] + v;
            lsum += res; lsq += res * res;
            g.ohh[tgt] = __float2half_rn(res);
        } else if (mode == EP_PV2) {
            int c  = 64 + (n >> 4);
            int py = (n >> 2) & 3, px = n & 3;
            int h = (m >> 4) * 4 + py, w = (m & 15) * 4 + px;
            long tgt = bbC + (long)c * HW + h * 64 + w;
            float res = g.xres[tgt] + v;
            lsum += res; lsq += res * res;
            g.ohh[tgt] = __float2half_rn(res);
        } else if (mode == EP_TANH) {
            g.ohh[bbC + li] = __float2half_rn(tanhf(v + g.bias[m]));
        } else if (mode == EP_GELU) {
            float u = v + g.bias[m];
            g.ohh[bbC + li] = __float2half_rn(0.5f * u * (1.f + erff(u * 0.70710678118654752f)));
        } else { // EP_FINAL
            long gi = bbC + li;
            g.of[gi] = __half2float(g.midh[gi]) * __half2float(g.gfh[gi]) + v + g.bias[m];
        }
    };

#pragma unroll
    for (int mt = 0; mt < 4; mt++) {
#pragma unroll
        for (int nt = 0; nt < 4; nt++) {
            int m1 = m0 + wm + mt * 16 + r;
            int m2 = m1 + 8;
            int nn = n0 + wn + nt * 8 + cg * 2;
            emit(acc[mt][nt][0], m1, nn);
            emit(acc[mt][nt][1], m1, nn + 1);
            emit(acc[mt][nt][2], m2, nn);
            emit(acc[mt][nt][3], m2, nn + 1);
        }
    }

    // ---- fused LN partial-stats reduction ----
    if (g.lng) {
#pragma unroll
        for (int o = 16; o; o >>= 1) {
            lsum += __shfl_xor_sync(0xffffffffu, lsum, o);
            lsq  += __shfl_xor_sync(0xffffffffu, lsq,  o);
        }
        float* smf = (float*)sm;
        if (lane == 0) { smf[warp * 2] = lsum; smf[warp * 2 + 1] = lsq; }
        __syncthreads();
        if (warp == 0 && lane < 8) {
            lsum = smf[lane * 2]; lsq = smf[lane * 2 + 1];
#pragma unroll
            for (int o = 4; o; o >>= 1) {
                lsum += __shfl_xor_sync(0xffu, lsum, o);
                lsq  += __shfl_xor_sync(0xffu, lsq,  o);
            }
            if (lane == 0) {
                int grp = (g.lng == 1) ? bb * 3 + (m0 >> 7) : bb;
                atomicAdd(&g.acc[2 * grp],     lsum);
                atomicAdd(&g.acc[2 * grp + 1], lsq);
            }
        }
    }
}

// ================= weight repack =================
__global__ void __launch_bounds__(256)
wconv_kernel(const float* qw, const float* kw, const float* vw,
             const float* e1, const float* s1, const float* b1,
             const float* e2, const float* s2, const float* b2,
             const float* sc, const float* bi1, const float* bi2) {
    int i = blockIdx.x * 256 + threadIdx.x;
    if (i >= W_TOTAL) return;
    float v;
    if (i < WO_E1) {
        int t = i >> 14, j = i & 16383;
        v = (t == 0 ? qw : t == 1 ? kw : vw)[j];
    } else if (i < WO_GB1) {
        int j = i - WO_E1, r = j / AUXK, c = j % AUXK;
        v = (c < AUXC) ? e1[r * AUXC + c] : 0.f;
    } else if (i < WO_B1) {
        int j = i - WO_GB1, r = j >> 7, c = j & 127;
        v = (r < 128) ? s1[r * 128 + c] : b1[(r - 128) * 256 + 128 + c];
    } else if (i < WO_E2) {
        v = b1[i - WO_B1];
    } else if (i < WO_GB2) {
        int j = i - WO_E2, r = j / AUXK, c = j % AUXK;
        v = (c < AUXC) ? e2[r * AUXC + c] : 0.f;
    } else if (i < WO_B2) {
        int j = i - WO_GB2, r = j >> 7, c = j & 127;
        v = (r < 128) ? s2[r * 128 + c] : b2[(r - 128) * 256 + 128 + c];
    } else if (i < WO_SC) {
        v = b2[i - WO_B2];
    } else {
        int j = i - WO_SC;
        int blk = j / 147456, t = j % 147456;
        int o = t / 1152, rr = t % 1152;
        int tap = rr >> 7, c = rr & 127;
        const float* w = (blk == 0 ? sc : blk == 1 ? bi1 : bi2);
        v = w[((o * 128 + c) * 3 + tap / 3) * 3 + (tap % 3)];
    }
    g_wh[i] = __float2half_rn(v);
}

__global__ void __launch_bounds__(256)
biaspack_kernel(const float* qb, const float* kb, const float* vb,
                const float* s1b, const float* b1b,
                const float* s2b, const float* b2b) {
    int i = blockIdx.x * 256 + threadIdx.x;
    if (i < 384) {
        g_qkvb[i] = i < 128 ? qb[i] : i < 256 ? kb[i - 128] : vb[i - 256];
    } else if (i < 640) {
        int j = i - 384;
        g_gbb1[j] = j < 128 ? s1b[j] : b1b[j - 128];
    } else if (i < 896) {
        int j = i - 640;
        g_gbb2[j] = j < 128 ? s2b[j] : b2b[j - 128];
    }
}

// ================= concat aux =================
__global__ void __launch_bounds__(256)
concat_aux_kernel(const float* __restrict__ edge, const float* __restrict__ seg,
                  const float* __restrict__ pe,   const float* __restrict__ ps) {
    int b = blockIdx.z;
    int c = blockIdx.y;
    int p0 = blockIdx.x * 2048 + threadIdx.x * 8;
    half* dst = g_auxh + ((long)b * AUXK + c) * HW + p0;
    half h[8];
    if (c < AUXC) {
        const float* src;
        if (c < 128)       src = edge + ((long)b * 128 + c) * HW;
        else if (c < 256)  src = seg  + ((long)b * 128 + (c - 128)) * HW;
        else if (c == 256) src = pe   + (long)b * HW;
        else               src = ps   + ((long)b * 20 + (c - 257)) * HW;
        float4 v0 = *(const float4*)(src + p0);
        float4 v1 = *(const float4*)(src + p0 + 4);
        h[0] = __float2half_rn(v0.x); h[1] = __float2half_rn(v0.y);
        h[2] = __float2half_rn(v0.z); h[3] = __float2half_rn(v0.w);
        h[4] = __float2half_rn(v1.x); h[5] = __float2half_rn(v1.y);
        h[6] = __float2half_rn(v1.z); h[7] = __float2half_rn(v1.w);
    } else {
#pragma unroll
        for (int j = 0; j < 8; j++) h[j] = __ushort_as_half((unsigned short)0);
    }
    *(uint4*)dst = *(uint4*)h;
}

__global__ void __launch_bounds__(256)
cvt_f2h_kernel(const float* __restrict__ src, half* __restrict__ dst, long n) {
    long i = ((long)blockIdx.x * 256 + threadIdx.x) * 8;
    if (i >= n) return;
    float4 v0 = *(const float4*)(src + i);
    float4 v1 = *(const float4*)(src + i + 4);
    half h[8];
    h[0] = __float2half_rn(v0.x); h[1] = __float2half_rn(v0.y);
    h[2] = __float2half_rn(v0.z); h[3] = __float2half_rn(v0.w);
    h[4] = __float2half_rn(v1.x); h[5] = __float2half_rn(v1.y);
    h[6] = __float2half_rn(v1.z); h[7] = __float2half_rn(v1.w);
    *(uint4*)(dst + i) = *(uint4*)h;
}

// ================= LN finalize =================
__global__ void ln_final_kernel() {
    int b = blockIdx.x;
    if (threadIdx.x == 0) {
        float s = g_acc[2 * b], q = g_acc[2 * b + 1];
        float mu = s / (float)CHW;
        float var = q / (float)CHW - mu * mu;
        g_stats[2 * b]     = mu;
        g_stats[2 * b + 1] = rsqrtf(var + 1e-5f);
    }
}

// ================= softmax (half in, half out) =================
__global__ void __launch_bounds__(256)
softmax_hh_kernel(const half* __restrict__ S, half* __restrict__ P, int L, int VPT) {
    long row = blockIdx.x;
    const half* p = S + row * (long)L;
    half* o = P + row * (long)L;
    int tid = threadIdx.x;
    __shared__ float sh[8];
    float v[4];
    for (int i = 0; i < VPT; i++) v[i] = __half2float(p[tid + i * 256]);

    float mx = -3.4e38f;
    for (int i = 0; i < VPT; i++) mx = fmaxf(mx, v[i]);
#pragma unroll
    for (int og = 16; og; og >>= 1) mx = fmaxf(mx, __shfl_xor_sync(0xffffffffu, mx, og));
    if ((tid & 31) == 0) sh[tid >> 5] = mx;
    __syncthreads();
    if (tid < 8) {
        float t = sh[tid];
#pragma unroll
        for (int og = 4; og; og >>= 1) t = fmaxf(t, __shfl_xor_sync(0xffu, t, og));
        if (tid == 0) sh[0] = t;
    }
    __syncthreads();
    mx = sh[0];
    __syncthreads();

    float s = 0.f;
    for (int i = 0; i < VPT; i++) { v[i] = __expf(v[i] - mx); s += v[i]; }
#pragma unroll
    for (int og = 16; og; og >>= 1) s += __shfl_xor_sync(0xffffffffu, s, og);
    if ((tid & 31) == 0) sh[tid >> 5] = s;
    __syncthreads();
    if (tid < 8) {
        float t = sh[tid];
#pragma unroll
        for (int og = 4; og; og >>= 1) t += __shfl_xor_sync(0xffu, t, og);
        if (tid == 0) sh[0] = t;
    }
    __syncthreads();
    float inv = 1.f / sh[0];
    for (int i = 0; i < VPT; i++) o[tid + i * 256] = __float2half_rn(v[i] * inv);
}

// ================= host =================
static void rung(bool transb, bool conv, int nT, int mT, int zT, const GP& g) {
    dim3 grid(nT, mT, zT);
    if (conv)        hgemm11<false, true ><<<grid, 256, GSM_BYTES>>>(g);
    else if (transb) hgemm11<true,  false><<<grid, 256, GSM_BYTES>>>(g);
    else             hgemm11<false, false><<<grid, 256, GSM_BYTES>>>(g);
}

extern "C" void kernel_launch(void* const* d_in, const int* in_sizes, int n_in,
                              void* d_out, int out_size) {
    const float* x    = (const float*)d_in[0];
    const float* edge = (const float*)d_in[1];
    const float* seg  = (const float*)d_in[2];
    const float* pe   = (const float*)d_in[3];
    const float* ps   = (const float*)d_in[4];
    const float* q_w  = (const float*)d_in[5];
    const float* q_b  = (const float*)d_in[6];
    const float* k_w  = (const float*)d_in[7];
    const float* k_b  = (const float*)d_in[8];
    const float* v_w  = (const float*)d_in[9];
    const float* v_b  = (const float*)d_in[10];
    const float* d1_embed_w = (const float*)d_in[11];
    const float* d1_embed_b = (const float*)d_in[12];
    const float* d1_scale_w = (const float*)d_in[13];
    const float* d1_scale_b = (const float*)d_in[14];
    const float* d1_bias_w  = (const float*)d_in[15];
    const float* d1_bias_b  = (const float*)d_in[16];
    const float* d2_embed_w = (const float*)d_in[17];
    const float* d2_embed_b = (const float*)d_in[18];
    const float* d2_scale_w = (const float*)d_in[19];
    const float* d2_scale_b = (const float*)d_in[20];
    const float* d2_bias_w  = (const float*)d_in[21];
    const float* d2_bias_b  = (const float*)d_in[22];
    const float* sc_w  = (const float*)d_in[23];
    const float* sc_b  = (const float*)d_in[24];
    const float* bi1_w = (const float*)d_in[25];
    const float* bi1_b = (const float*)d_in[26];
    const float* bi2_w = (const float*)d_in[27];
    const float* bi2_b = (const float*)d_in[28];
    float* out = (float*)d_out;

    cudaFuncSetAttribute(hgemm11<false, false>, cudaFuncAttributeMaxDynamicSharedMemorySize, GSM_BYTES);
    cudaFuncSetAttribute(hgemm11<true,  false>, cudaFuncAttributeMaxDynamicSharedMemorySize, GSM_BYTES);
    cudaFuncSetAttribute(hgemm11<false, true >, cudaFuncAttributeMaxDynamicSharedMemorySize, GSM_BYTES);

    half *wh, *auxh, *xh, *ah, *t0h, *gamh, *beth, *midh, *oh, *gfh, *tmph;
    half *qp1, *kp1, *vp1, *qp2, *kp2, *vp2, *s1h, *s2h;
    float *stats, *acc, *qkvb, *gbb1, *gbb2;
    cudaGetSymbolAddress((void**)&wh,   g_wh);
    cudaGetSymbolAddress((void**)&auxh, g_auxh);
    cudaGetSymbolAddress((void**)&xh,   g_xh);
    cudaGetSymbolAddress((void**)&ah,   g_ah);
    cudaGetSymbolAddress((void**)&t0h,  g_t0h);
    cudaGetSymbolAddress((void**)&gamh, g_gamh);
    cudaGetSymbolAddress((void**)&beth, g_beth);
    cudaGetSymbolAddress((void**)&midh, g_midh);
    cudaGetSymbolAddress((void**)&oh,   g_oh);
    cudaGetSymbolAddress((void**)&gfh,  g_gfh);
    cudaGetSymbolAddress((void**)&tmph, g_tmph);
    cudaGetSymbolAddress((void**)&qp1,  g_qp1);
    cudaGetSymbolAddress((void**)&kp1,  g_kp1);
    cudaGetSymbolAddress((void**)&vp1,  g_vp1);
    cudaGetSymbolAddress((void**)&qp2,  g_qp2);
    cudaGetSymbolAddress((void**)&kp2,  g_kp2);
    cudaGetSymbolAddress((void**)&vp2,  g_vp2);
    cudaGetSymbolAddress((void**)&s1h,  g_s1h);
    cudaGetSymbolAddress((void**)&s2h,  g_s2h);
    cudaGetSymbolAddress((void**)&stats, g_stats);
    cudaGetSymbolAddress((void**)&acc,   g_acc);
    cudaGetSymbolAddress((void**)&qkvb, g_qkvb);
    cudaGetSymbolAddress((void**)&gbb1, g_gbb1);
    cudaGetSymbolAddress((void**)&gbb2, g_gbb2);

    // 0. conversions / packing
    wconv_kernel<<<(W_TOTAL + 255) / 256, 256>>>(q_w, k_w, v_w,
                                                 d1_embed_w, d1_scale_w, d1_bias_w,
                                                 d2_embed_w, d2_scale_w, d2_bias_w,
                                                 sc_w, bi1_w, bi2_w);
    biaspack_kernel<<<4, 256>>>(q_b, k_b, v_b, d1_scale_b, d1_bias_b, d2_scale_b, d2_bias_b);
    cvt_f2h_kernel<<<(int)(((long)NB * CHW / 8 + 255) / 256), 256>>>(x, xh, (long)NB * CHW);
    concat_aux_kernel<<<dim3(2, AUXK, NB), 256>>>(edge, seg, pe, ps);

    // 1. ADN-1 shared
    {
        GP p = {};
        p.A = wh + WO_E1; p.lda = AUXK; p.sA = 0;
        p.B = auxh; p.ldb = HW; p.sB = (long)AUXK * HW;
        p.N = HW; p.sC = CHW; p.nkt = AUXK / 64; p.mode = EP_LIN;
        p.bias = d1_embed_b; p.ohh = ah;
        rung(false, false, 32, 1, NB, p);
    }
    {
        GP p = {};
        p.A = wh + WO_GB1; p.lda = 128; p.sA = 0;
        p.B = ah; p.ldb = HW; p.sB = CHW;
        p.N = HW; p.sC = CHW; p.nkt = 2; p.mode = EP_GB;
        p.bias = gbb1; p.ohh = gamh; p.ohh2 = beth;
        rung(false, false, 32, 2, NB, p);
    }

    // 2. q/k/v conv1x1 merged (M=384), fused LN stats
    cudaMemsetAsync(acc, 0, 96 * sizeof(float));
    {
        GP p = {};
        p.A = wh + WO_QKV; p.lda = 128; p.sA = 0;
        p.B = xh; p.ldb = HW; p.sB = CHW;
        p.N = HW; p.sC = 3L * CHW; p.nkt = 2; p.mode = EP_LIN; p.lng = 1;
        p.bias = qkvb; p.ohh = t0h; p.acc = acc;
        rung(false, false, 32, 3, NB, p);
    }
    ln_final_kernel<<<48, 32>>>();

    // 3. ADN-apply merged (48 z), fused patched writes
    {
        GP p = {};
        p.A = wh + WO_B1; p.lda = 256; p.sA = 0;
        p.B = t0h; p.ldb = HW; p.sB = CHW;
        p.N = HW; p.sC = CHW; p.nkt = 2; p.mode = EP_QKV3;
        p.t0h = t0h; p.gamh = gamh; p.beth = beth; p.stats = stats;
        p.d1q = qp1; p.d1k = kp1; p.d1v = vp1;
        p.d2q = qp2; p.d2k = kp2; p.d2v = vp2;
        rung(false, false, 32, 1, 48, p);
    }

    // 4. attention scale 1
    {
        GP p = {};
        p.A = qp1; p.lda = 256; p.sA = 1024L * 256;
        p.B = kp1; p.ldb = 256; p.sB = 1024L * 256;
        p.N = 1024; p.sC = 1024L * 1024; p.nkt = 4; p.mode = EP_SCORE; p.scale = 0.0625f;
        p.ohh = s1h;
        rung(true, false, 8, 8, NB, p);
    }
    softmax_hh_kernel<<<NB * 1024, 256>>>(s1h, s1h, 1024, 4);
    cudaMemsetAsync(acc, 0, 32 * sizeof(float));
    {
        GP p = {};
        p.A = s1h; p.lda = 1024; p.sA = 1024L * 1024;
        p.B = vp1; p.ldb = 256; p.sB = 1024L * 256;
        p.N = 256; p.sC = CHW; p.nkt = 16; p.mode = EP_PV1; p.lng = 2;
        p.xres = x; p.ohh = midh; p.acc = acc;
        rung(false, false, 2, 8, NB, p);
    }

    // 5. attention scale 2
    {
        GP p = {};
        p.A = qp2; p.lda = 1024; p.sA = 256L * 1024;
        p.B = kp2; p.ldb = 1024; p.sB = 256L * 1024;
        p.N = 256; p.sC = 256L * 256; p.nkt = 16; p.mode = EP_SCORE; p.scale = 0.03125f;
        p.ohh = s2h;
        rung(true, false, 2, 2, NB, p);
    }
    softmax_hh_kernel<<<NB * 256, 256>>>(s2h, s2h, 256, 1);
    {
        GP p = {};
        p.A = s2h; p.lda = 256; p.sA = 256L * 256;
        p.B = vp2; p.ldb = 1024; p.sB = 256L * 1024;
        p.N = 1024; p.sC = CHW; p.nkt = 4; p.mode = EP_PV2; p.lng = 2;
        p.xres = x; p.ohh = midh; p.acc = acc;
        rung(false, false, 8, 2, NB, p);
    }
    ln_final_kernel<<<16, 32>>>();

    // 6. ADN-2
    {
        GP p = {};
        p.A = wh + WO_E2; p.lda = AUXK; p.sA = 0;
        p.B = auxh; p.ldb = HW; p.sB = (long)AUXK * HW;
        p.N = HW; p.sC = CHW; p.nkt = AUXK / 64; p.mode = EP_LIN;
        p.bias = d2_embed_b; p.ohh = ah;
        rung(false, false, 32, 1, NB, p);
    }
    {
        GP p = {};
        p.A = wh + WO_GB2; p.lda = 128; p.sA = 0;
        p.B = ah; p.ldb = HW; p.sB = CHW;
        p.N = HW; p.sC = CHW; p.nkt = 2; p.mode = EP_GB;
        p.bias = gbb2; p.ohh = gamh; p.ohh2 = beth;
        rung(false, false, 32, 2, NB, p);
    }
    {
        GP p = {};
        p.A = wh + WO_B2; p.lda = 256; p.sA = 0;
        p.B = midh; p.ldb = HW; p.sB = CHW;
        p.N = HW; p.sC = CHW; p.nkt = 2; p.mode = EP_ADN;
        p.t0h = midh; p.gamh = gamh; p.beth = beth; p.stats = stats;
        p.ohh = oh;
        rung(false, false, 32, 1, NB, p);
    }

    // 7. conv3x3 chain (vectorized gather, K=1152)
    {
        GP p = {};
        p.A = wh + WO_SC; p.lda = 1152; p.sA = 0;
        p.B = oh; p.ldb = 0; p.sB = CHW;
        p.N = HW; p.sC = CHW; p.nkt = 18; p.mode = EP_TANH; p.dil = 1;
        p.bias = sc_b; p.ohh = gfh;
        rung(false, true, 32, 1, NB, p);
    }
    {
        GP p = {};
        p.A = wh + WO_BI1; p.lda = 1152; p.sA = 0;
        p.B = oh; p.ldb = 0; p.sB = CHW;
        p.N = HW; p.sC = CHW; p.nkt = 18; p.mode = EP_GELU; p.dil = 2;
        p.bias = bi1_b; p.ohh = tmph;
        rung(false, true, 32, 1, NB, p);
    }
    {
        GP p = {};
        p.A = wh + WO_BI2; p.lda = 1152; p.sA = 0;
        p.B = tmph; p.ldb = 0; p.sB = CHW;
        p.N = HW; p.sC = CHW; p.nkt = 18; p.mode = EP_FINAL; p.dil = 1;
        p.bias = bi2_b; p.midh = midh; p.gfh = gfh; p.of = out;
        rung(false, true, 32, 1, NB, p);
    }
}